// round 1
// baseline (speedup 1.0000x reference)
#include <cuda_runtime.h>

// out[b,i] = sum_h W2[i,h] * relu( sum_d X[b,d] * Adj[i,d] * W1[i,h,d] )
// B=16384, D=64, H=64.
// One block = (node i, 128-row batch tile). 256 threads: tx=tid&15 owns 4 h
// (h = 4*tx..4*tx+3), ty=tid>>4 owns 8 batch rows. Accumulators are packed
// f32x2 pairs driven by fma.rn.f32x2 (FFMA2).

#define NT 256
#define TB 128
#define WPAD 68   // WsT row stride in floats (16B-aligned, kills STS conflicts)

__device__ __forceinline__ unsigned long long pack2(float v) {
    unsigned long long r;
    unsigned u = __float_as_uint(v);
    asm("mov.b64 %0, {%1, %1};" : "=l"(r) : "r"(u));
    return r;
}

__device__ __forceinline__ void fma2(unsigned long long& d,
                                     unsigned long long a,
                                     unsigned long long b) {
    asm("fma.rn.f32x2 %0, %1, %2, %0;" : "+l"(d) : "l"(a), "l"(b));
}

__device__ __forceinline__ void unpack2(unsigned long long v, float& lo, float& hi) {
    unsigned a, b;
    asm("mov.b64 {%0, %1}, %2;" : "=r"(a), "=r"(b) : "l"(v));
    lo = __uint_as_float(a);
    hi = __uint_as_float(b);
}

__global__ __launch_bounds__(NT, 2)
void tp_kernel(const float* __restrict__ X,
               const float* __restrict__ Adj,
               const float* __restrict__ W1,
               const float* __restrict__ W2,
               float* __restrict__ out)
{
    __shared__ float WsT[64 * WPAD];   // WsT[d*WPAD + h] = W1[i,h,d]*Adj[i,d]

    const int i    = blockIdx.x;       // node 0..63 (fastest -> L2 reuse of X tile)
    const int row0 = blockIdx.y * TB;  // batch tile
    const int tid  = threadIdx.x;

    // Fold adjacency into W1 and transpose into smem.
    // Global reads coalesced (d fastest); STS 4-way conflicted (one-time).
    {
        const float* W1i  = W1  + (i << 12);
        const float* Adji = Adj + (i << 6);
        #pragma unroll
        for (int j = tid; j < 4096; j += NT) {
            int d = j & 63;
            int h = j >> 6;
            WsT[d * WPAD + h] = W1i[j] * Adji[d];
        }
    }
    __syncthreads();

    const int tx = tid & 15;   // h-group: h = 4*tx .. 4*tx+3
    const int ty = tid >> 4;   // row-group: rows ty*8 .. ty*8+7
    const float* Xb = X + (size_t)(row0 + ty * 8) * 64;

    // acc[r][0] = (h0,h1) pair, acc[r][1] = (h2,h3) pair, fp32 each lane.
    unsigned long long acc[8][2];
    #pragma unroll
    for (int r = 0; r < 8; ++r) { acc[r][0] = 0ull; acc[r][1] = 0ull; }

    #pragma unroll 4
    for (int d4 = 0; d4 < 16; ++d4) {
        // Weight pairs for 4 consecutive d, this thread's 4 h.
        // LDS.128, conflict-free (lanes cover all 32 banks; half-warp broadcast).
        ulonglong2 w0 = *(const ulonglong2*)&WsT[(4 * d4 + 0) * WPAD + 4 * tx];
        ulonglong2 w1 = *(const ulonglong2*)&WsT[(4 * d4 + 1) * WPAD + 4 * tx];
        ulonglong2 w2 = *(const ulonglong2*)&WsT[(4 * d4 + 2) * WPAD + 4 * tx];
        ulonglong2 w3 = *(const ulonglong2*)&WsT[(4 * d4 + 3) * WPAD + 4 * tx];

        #pragma unroll
        for (int r = 0; r < 8; ++r) {
            // L1-resident; same address across the 16 tx lanes -> broadcast.
            float4 xv = *(const float4*)(Xb + r * 64 + 4 * d4);
            unsigned long long x0 = pack2(xv.x);
            unsigned long long x1 = pack2(xv.y);
            unsigned long long x2 = pack2(xv.z);
            unsigned long long x3 = pack2(xv.w);
            fma2(acc[r][0], x0, w0.x);  fma2(acc[r][1], x0, w0.y);
            fma2(acc[r][0], x1, w1.x);  fma2(acc[r][1], x1, w1.y);
            fma2(acc[r][0], x2, w2.x);  fma2(acc[r][1], x2, w2.y);
            fma2(acc[r][0], x3, w3.x);  fma2(acc[r][1], x3, w3.y);
        }
    }

    // Epilogue: relu -> dot with W2[i, 4tx..4tx+3] -> reduce over the 16 tx lanes.
    const float4 w2v = *(const float4*)(W2 + (i << 6) + 4 * tx);
    #pragma unroll
    for (int r = 0; r < 8; ++r) {
        float a0, a1, a2, a3;
        unpack2(acc[r][0], a0, a1);
        unpack2(acc[r][1], a2, a3);
        float p = fmaxf(a0, 0.f) * w2v.x
                + fmaxf(a1, 0.f) * w2v.y
                + fmaxf(a2, 0.f) * w2v.z
                + fmaxf(a3, 0.f) * w2v.w;
        // xor<=8 keeps the shuffle within each 16-lane (tx) half of the warp.
        p += __shfl_xor_sync(0xffffffffu, p, 8);
        p += __shfl_xor_sync(0xffffffffu, p, 4);
        p += __shfl_xor_sync(0xffffffffu, p, 2);
        p += __shfl_xor_sync(0xffffffffu, p, 1);
        if (tx == 0)
            out[(size_t)(row0 + ty * 8 + r) * 64 + i] = p;
    }
}

extern "C" void kernel_launch(void* const* d_in, const int* in_sizes, int n_in,
                              void* d_out, int out_size) {
    const float* X   = (const float*)d_in[0];  // [16384, 64]
    const float* Adj = (const float*)d_in[1];  // [64, 64]
    const float* W1  = (const float*)d_in[2];  // [64, 64, 64] (i, h, d)
    const float* W2  = (const float*)d_in[3];  // [64, 64]     (i, h)
    float* out = (float*)d_out;                // [16384, 64]

    dim3 grid(64, 16384 / TB);  // x = node (fastest -> shared X tile in L2)
    tp_kernel<<<grid, NT>>>(X, Adj, W1, W2, out);
}

// round 2
// speedup vs baseline: 1.0265x; 1.0265x over previous
#include <cuda_runtime.h>

// out[b,i] = sum_h W2[i,h] * relu( sum_d X[b,d]*Adj[i,d]*W1[i,h,d] )
// B=16384, D=64, H=64.
//
// Block = (4 nodes, 128 batch rows), 256 threads = 8 tx (h-groups of 8) x 32 ty.
// Each thread: 8 h x 4 rows. Accumulators are f32x2 (even-d sum, odd-d sum)
// pairs -> x float4 and native-layout W float4 ARE the packed operands
// (no pack MOVs). X staged in smem once per block (reused by 4 nodes),
// W' = W1*adj staged per node. Both xor-swizzled for 1-wavefront LDS.128.

#define NT  256
#define TB  128
#define NPB 4

__device__ __forceinline__ void fma2(unsigned long long& d,
                                     unsigned long long a,
                                     unsigned long long b) {
    asm("fma.rn.f32x2 %0, %1, %2, %0;" : "+l"(d) : "l"(a), "l"(b));
}

__device__ __forceinline__ float2 up2(unsigned long long v) {
    unsigned a, b;
    asm("mov.b64 {%0, %1}, %2;" : "=r"(a), "=r"(b) : "l"(v));
    float2 f;
    f.x = __uint_as_float(a);
    f.y = __uint_as_float(b);
    return f;
}

__global__ __launch_bounds__(NT, 2)
void tp_kernel(const float* __restrict__ X,
               const float* __restrict__ Adj,
               const float* __restrict__ W1,
               const float* __restrict__ W2,
               float* __restrict__ out)
{
    __shared__ float4 Xs4[TB * 16];   // 32KB: X tile, slot (row,d4) at row*16 + (d4 ^ (row&15))
    __shared__ float4 Ws4[64 * 16];   // 16KB: W'[h][4d], slot d4*64 + (h&7)*8 + ((h>>3) ^ (d4&7))

    const int tid  = threadIdx.x;
    const int tx   = tid & 7;        // h-group: h = 8*tx .. 8*tx+7
    const int ty   = tid >> 3;       // rows ty, ty+32, ty+64, ty+96
    const int row0 = blockIdx.y * TB;
    const int i0   = blockIdx.x * NPB;

    // ---- Stage X tile (coalesced LDG.128, 2-way-max STS) ----
    {
        const float4* Xg = (const float4*)(X + (size_t)row0 * 64);
        #pragma unroll
        for (int j = tid; j < TB * 16; j += NT) {
            int row = j >> 4, d4 = j & 15;
            Xs4[(row << 4) + (d4 ^ (row & 15))] = Xg[j];
        }
    }

    const int xsw = ty & 15;

    for (int n = 0; n < NPB; ++n) {
        const int i = i0 + n;

        // ---- Fill W' = W1[i] * adj[i] (coalesced read, native [h][d] order) ----
        {
            const float4* W1i = (const float4*)(W1 + ((size_t)i << 12));
            const float4* A4  = (const float4*)(Adj + (i << 6));
            #pragma unroll
            for (int j = tid; j < 1024; j += NT) {
                int h = j >> 4, d4 = j & 15;
                float4 w = W1i[j];
                float4 a = A4[d4];
                w.x *= a.x; w.y *= a.y; w.z *= a.z; w.w *= a.w;
                Ws4[(d4 << 6) + ((h & 7) << 3) + ((h >> 3) ^ (d4 & 7))] = w;
            }
        }
        __syncthreads();

        // acc[r][j] = f32x2 (sum over even d, sum over odd d) for h = 8*tx+j
        unsigned long long acc[4][8];
        #pragma unroll
        for (int r = 0; r < 4; ++r)
            #pragma unroll
            for (int j = 0; j < 8; ++j)
                acc[r][j] = 0ull;

        #pragma unroll 1
        for (int d4 = 0; d4 < 16; ++d4) {
            const int txw  = tx ^ (d4 & 7);
            const int wbase = (d4 << 6) + txw;

            ulonglong2 xv[4];
            #pragma unroll
            for (int r = 0; r < 4; ++r) {
                int row = ty + (r << 5);
                xv[r] = ((const ulonglong2*)Xs4)[(row << 4) + (d4 ^ xsw)];
            }

            #pragma unroll
            for (int j4 = 0; j4 < 2; ++j4) {
                ulonglong2 wv[4];
                #pragma unroll
                for (int j = 0; j < 4; ++j)
                    wv[j] = ((const ulonglong2*)Ws4)[wbase + ((j4 * 4 + j) << 3)];
                #pragma unroll
                for (int r = 0; r < 4; ++r)
                    #pragma unroll
                    for (int j = 0; j < 4; ++j) {
                        fma2(acc[r][j4 * 4 + j], xv[r].x, wv[j].x);
                        fma2(acc[r][j4 * 4 + j], xv[r].y, wv[j].y);
                    }
            }
        }

        // ---- Epilogue: relu(sum_even+sum_odd) dot W2, reduce over 8 tx lanes ----
        const float4 w2a = *(const float4*)(W2 + (i << 6) + tx * 8);
        const float4 w2b = *(const float4*)(W2 + (i << 6) + tx * 8 + 4);
        const float w2s[8] = {w2a.x, w2a.y, w2a.z, w2a.w,
                              w2b.x, w2b.y, w2b.z, w2b.w};
        #pragma unroll
        for (int r = 0; r < 4; ++r) {
            float s = 0.f;
            #pragma unroll
            for (int j = 0; j < 8; ++j) {
                float2 p = up2(acc[r][j]);
                s = fmaf(fmaxf(p.x + p.y, 0.f), w2s[j], s);
            }
            s += __shfl_xor_sync(0xffffffffu, s, 1);
            s += __shfl_xor_sync(0xffffffffu, s, 2);
            s += __shfl_xor_sync(0xffffffffu, s, 4);
            if (tx == 0)
                out[(size_t)(row0 + ty + (r << 5)) * 64 + i] = s;
        }
        __syncthreads();   // Ws reused next node
    }
}

extern "C" void kernel_launch(void* const* d_in, const int* in_sizes, int n_in,
                              void* d_out, int out_size) {
    const float* X   = (const float*)d_in[0];  // [16384, 64]
    const float* Adj = (const float*)d_in[1];  // [64, 64]
    const float* W1  = (const float*)d_in[2];  // [64, 64, 64] (i, h, d)
    const float* W2  = (const float*)d_in[3];  // [64, 64]     (i, h)
    float* out = (float*)d_out;                // [16384, 64]

    dim3 grid(64 / NPB, 16384 / TB);
    tp_kernel<<<grid, NT>>>(X, Adj, W1, W2, out);
}

// round 4
// speedup vs baseline: 3.4314x; 3.3427x over previous
#include <cuda_runtime.h>
#include <cuda_bf16.h>
#include <cstdint>

// out[b,i] = sum_h W2[i,h] * relu( sum_d X[b,d]*Adj[i,d]*W1[i,h,d] )
// B=16384, D=64, H=64.
//
// Plan: bf16 split precision on the HMMA pipe (mma.sync m16n8k16, base PTX —
// tcgen05 is unavailable because harness PTX targets compute_103 without 'a').
//   acc_f32 += Xhi*Whi + Xhi*Wlo + Xlo*Whi     (lo*lo dropped, ~2^-16)
// Prep kernel decomposes X and W'=W1*adj into bf16 hi/lo ONCE (device globals).
// Main kernel: block = (2 nodes, 128 rows), 8 warps; warp = 32 rows x 64 h.

#define NT  256
#define NPB 2
#define TB  128

// ---- device-global bf16 hi/lo buffers (prep kernel output) ----
static __device__ __align__(16) __nv_bfloat16 Xhi_g[16384 * 64];
static __device__ __align__(16) __nv_bfloat16 Xlo_g[16384 * 64];
static __device__ __align__(16) __nv_bfloat16 Whi_g[64 * 64 * 64];
static __device__ __align__(16) __nv_bfloat16 Wlo_g[64 * 64 * 64];

// ---- main-kernel smem layout (bytes) ----
#define OFF_W2   0        // 128 floats
#define OFF_XHI  1024     // 128 rows x 128B, SW128
#define OFF_XLO  17408    // = OFF_XHI + 16384 (lo = hi + 16384 everywhere)
#define OFF_W    33792    // 2 nodes x (hi 8KB, lo 8KB)
#define SMEM_TOTAL 66560

static __device__ __forceinline__ uint32_t smem_u32(const void* p) {
    uint32_t a;
    asm("{ .reg .u64 t; cvta.to.shared.u64 t, %1; cvt.u32.u64 %0, t; }" : "=r"(a) : "l"(p));
    return a;
}

static __device__ __forceinline__ void ldsm4(uint32_t* r, uint32_t addr) {
    asm volatile("ldmatrix.sync.aligned.m8n8.x4.shared.b16 {%0,%1,%2,%3}, [%4];"
                 : "=r"(r[0]), "=r"(r[1]), "=r"(r[2]), "=r"(r[3]) : "r"(addr));
}

static __device__ __forceinline__ void mma16816(float* c, const uint32_t* a,
                                                const uint32_t* b) {
    asm volatile(
        "mma.sync.aligned.m16n8k16.row.col.f32.bf16.bf16.f32 "
        "{%0,%1,%2,%3}, {%4,%5,%6,%7}, {%8,%9}, {%0,%1,%2,%3};"
        : "+f"(c[0]), "+f"(c[1]), "+f"(c[2]), "+f"(c[3])
        : "r"(a[0]), "r"(a[1]), "r"(a[2]), "r"(a[3]), "r"(b[0]), "r"(b[1]));
}

// hi/lo bf16 split of a float4 -> two packed uint2 (4 bf16 each)
static __device__ __forceinline__ void split4(float4 v, uint2& hi, uint2& lo) {
    __nv_bfloat16 h0 = __float2bfloat16_rn(v.x), h1 = __float2bfloat16_rn(v.y);
    __nv_bfloat16 h2 = __float2bfloat16_rn(v.z), h3 = __float2bfloat16_rn(v.w);
    __nv_bfloat162 hp0; hp0.x = h0; hp0.y = h1;
    __nv_bfloat162 hp1; hp1.x = h2; hp1.y = h3;
    __nv_bfloat162 lp0 = __floats2bfloat162_rn(v.x - __bfloat162float(h0),
                                               v.y - __bfloat162float(h1));
    __nv_bfloat162 lp1 = __floats2bfloat162_rn(v.z - __bfloat162float(h2),
                                               v.w - __bfloat162float(h3));
    hi.x = *(uint32_t*)&hp0; hi.y = *(uint32_t*)&hp1;
    lo.x = *(uint32_t*)&lp0; lo.y = *(uint32_t*)&lp1;
}

// ---- prep: decompose X and W1*adj into bf16 hi/lo ----
__global__ __launch_bounds__(NT)
void prep_kernel(const float* __restrict__ X,
                 const float* __restrict__ Adj,
                 const float* __restrict__ W1)
{
    int gid = blockIdx.x * NT + threadIdx.x;
    if (gid < 262144) {                       // X: 16384*64/4 float4s
        float4 v = ((const float4*)X)[gid];
        uint2 hi, lo;
        split4(v, hi, lo);
        ((uint2*)Xhi_g)[gid] = hi;
        ((uint2*)Xlo_g)[gid] = lo;
    } else {                                  // W: 64*64*64/4 float4s
        int j = gid - 262144;                 // 0..65535
        int i  = j >> 10;
        int d4 = j & 15;
        float4 v = ((const float4*)W1)[j];
        float4 a = ((const float4*)Adj)[i * 16 + d4];
        v.x *= a.x; v.y *= a.y; v.z *= a.z; v.w *= a.w;
        uint2 hi, lo;
        split4(v, hi, lo);
        ((uint2*)Whi_g)[j] = hi;
        ((uint2*)Wlo_g)[j] = lo;
    }
}

// ---- main GEMM ----
__global__ __launch_bounds__(NT, 2)
void tp_kernel(const float* __restrict__ W2, float* __restrict__ out)
{
    extern __shared__ char smem[];
    const uint32_t sb = smem_u32(smem);
    const int tid = threadIdx.x;
    const int wid = tid >> 5;
    const int l   = tid & 31;
    const int i0   = blockIdx.x * NPB;     // node pair (fastest -> X L2 reuse)
    const int row0 = blockIdx.y * TB;

    // ---- stage W2 ----
    if (tid < 128) ((float*)(smem + OFF_W2))[tid] = W2[i0 * 64 + tid];

    // ---- stage X hi/lo tile (swizzled 16B chunks) ----
    {
        const uint4* srcHi = (const uint4*)Xhi_g + row0 * 8;
        const uint4* srcLo = (const uint4*)Xlo_g + row0 * 8;
        #pragma unroll
        for (int it = 0; it < 4; ++it) {
            int c   = tid + it * NT;       // 0..1023
            int row = c >> 3, k16 = c & 7;
            uint32_t dst = OFF_XHI + row * 128 + ((k16 ^ (row & 7)) << 4);
            *(uint4*)(smem + dst)         = srcHi[c];
            *(uint4*)(smem + dst + 16384) = srcLo[c];
        }
    }
    // ---- stage W hi/lo for 2 nodes ----
    {
        #pragma unroll
        for (int it = 0; it < 8; ++it) {
            int c  = tid + it * NT;        // 0..2047
            int n  = c >> 10, hl = (c >> 9) & 1, r = (c >> 3) & 63, k16 = c & 7;
            const uint4* src = (const uint4*)(hl ? Wlo_g : Whi_g)
                             + ((i0 + n) * 64 + r) * 8 + k16;
            uint32_t dst = OFF_W + n * 16384 + hl * 8192 + r * 128
                         + ((k16 ^ (r & 7)) << 4);
            *(uint4*)(smem + dst) = *src;
        }
    }
    __syncthreads();

    // ---- per-warp tile: node = wid>>2, rows rowbase..+31 ----
    const int node    = wid >> 2;
    const int rowbase = (wid & 3) * 32;

    // ldmatrix lane address pre-computation
    // A (16x16 m-tiles): lane -> row rowbase+mt*16+(l&15), chunk half l>>4
    uint32_t aoff[2], asw[2];
    #pragma unroll
    for (int mt = 0; mt < 2; ++mt) {
        int arow = rowbase + mt * 16 + (l & 15);
        aoff[mt] = sb + OFF_XHI + arow * 128;
        asw[mt]  = arow & 7;
    }
    const uint32_t ahalf = (l >> 4) & 1;
    // B (16n x 16k groups): lane -> n-row, chunk half (l>>3)&1
    uint32_t boff[4], bsw[4];
    #pragma unroll
    for (int g = 0; g < 4; ++g) {
        int brow = g * 16 + ((l >> 4) & 1) * 8 + (l & 7);
        boff[g] = sb + OFF_W + node * 16384 + brow * 128;
        bsw[g]  = brow & 7;
    }
    const uint32_t bhalf = (l >> 3) & 1;

    float acc[2][8][4];
    #pragma unroll
    for (int mt = 0; mt < 2; ++mt)
        #pragma unroll
        for (int n = 0; n < 8; ++n)
            #pragma unroll
            for (int q = 0; q < 4; ++q) acc[mt][n][q] = 0.f;

    #pragma unroll
    for (int ks = 0; ks < 4; ++ks) {
        uint32_t xhi[2][4], xlo[2][4];
        #pragma unroll
        for (int mt = 0; mt < 2; ++mt) {
            uint32_t addr = aoff[mt] + (((ks * 2 + ahalf) ^ asw[mt]) << 4);
            ldsm4(xhi[mt], addr);
            ldsm4(xlo[mt], addr + 16384);
        }
        #pragma unroll
        for (int gp = 0; gp < 2; ++gp) {
            uint32_t whi[2][4], wlo[2][4];
            #pragma unroll
            for (int gg = 0; gg < 2; ++gg) {
                int g = gp * 2 + gg;
                uint32_t addr = boff[g] + (((ks * 2 + bhalf) ^ bsw[g]) << 4);
                ldsm4(whi[gg], addr);
                ldsm4(wlo[gg], addr + 8192);
            }
            #pragma unroll
            for (int mt = 0; mt < 2; ++mt)
                #pragma unroll
                for (int tt = 0; tt < 4; ++tt) {
                    int n = gp * 4 + tt;
                    const uint32_t* bh = &whi[tt >> 1][(tt & 1) * 2];
                    const uint32_t* bl = &wlo[tt >> 1][(tt & 1) * 2];
                    mma16816(acc[mt][n], xhi[mt], bh);
                    mma16816(acc[mt][n], xhi[mt], bl);
                    mma16816(acc[mt][n], xlo[mt], bh);
                }
        }
    }

    // ---- epilogue: relu + dot W2, reduce across lane quads, store ----
    const float* W2s = (const float*)(smem + OFF_W2) + node * 64;
    #pragma unroll
    for (int mt = 0; mt < 2; ++mt) {
        float s0 = 0.f, s1 = 0.f;
        #pragma unroll
        for (int n = 0; n < 8; ++n) {
            float2 w = *(const float2*)(W2s + n * 8 + (l & 3) * 2);
            s0 = fmaf(fmaxf(acc[mt][n][0], 0.f), w.x, s0);
            s0 = fmaf(fmaxf(acc[mt][n][1], 0.f), w.y, s0);
            s1 = fmaf(fmaxf(acc[mt][n][2], 0.f), w.x, s1);
            s1 = fmaf(fmaxf(acc[mt][n][3], 0.f), w.y, s1);
        }
        s0 += __shfl_xor_sync(0xffffffffu, s0, 1);
        s0 += __shfl_xor_sync(0xffffffffu, s0, 2);
        s1 += __shfl_xor_sync(0xffffffffu, s1, 1);
        s1 += __shfl_xor_sync(0xffffffffu, s1, 2);
        if ((l & 3) == 0) {
            int grow = row0 + rowbase + mt * 16 + (l >> 2);
            out[(size_t)grow * 64 + i0 + node]       = s0;
            out[(size_t)(grow + 8) * 64 + i0 + node] = s1;
        }
    }
}

extern "C" void kernel_launch(void* const* d_in, const int* in_sizes, int n_in,
                              void* d_out, int out_size) {
    const float* X   = (const float*)d_in[0];  // [16384, 64]
    const float* Adj = (const float*)d_in[1];  // [64, 64]
    const float* W1  = (const float*)d_in[2];  // [64, 64, 64] (i,h,d)
    const float* W2  = (const float*)d_in[3];  // [64, 64]
    float* out = (float*)d_out;                // [16384, 64]

    prep_kernel<<<1280, NT>>>(X, Adj, W1);

    static bool attr_set = false;
    if (!attr_set) {
        cudaFuncSetAttribute(tp_kernel, cudaFuncAttributeMaxDynamicSharedMemorySize,
                             SMEM_TOTAL);
        attr_set = true;
    }
    dim3 grid(64 / NPB, 16384 / TB);
    tp_kernel<<<grid, NT, SMEM_TOTAL>>>(W2, out);
}

// round 5
// speedup vs baseline: 4.4359x; 1.2927x over previous
#include <cuda_runtime.h>
#include <cuda_fp16.h>
#include <cstdint>

// out[b,i] = sum_h W2[i,h] * relu( sum_d X[b,d]*Adj[i,d]*W1[i,h,d] )
// B=16384, D=64, H=64.
//
// fp16 2-term split-precision on the HMMA pipe (mma.sync m16n8k16 f32.f16.f16):
//   acc_f32 += Xhi*Wf + Xlo*Wf      (x = xhi + xlo exact to 2^-22; Wf = fp16(W1*adj),
//                                    rounding 2^-11 -> rel_err ~1e-4)
// Prep kernel decomposes X (hi/lo fp16) and W'=W1*adj (single fp16) once.
// Main: block = (2 nodes, 128 rows), 8 warps; warp = 32 rows x 64 h, both terms
// share B fragments in registers.

#define NT  256
#define NPB 2
#define TB  128

// ---- device-global fp16 buffers (prep output) ----
static __device__ __align__(16) __half Xhi_g[16384 * 64];
static __device__ __align__(16) __half Xlo_g[16384 * 64];
static __device__ __align__(16) __half Wf_g[64 * 64 * 64];

// ---- main-kernel smem layout (bytes) ----
#define OFF_W2   0        // 128 floats
#define OFF_XHI  1024     // 128 rows x 128B, SW-swizzled
#define OFF_XLO  17408    // = OFF_XHI + 16384
#define OFF_W    33792    // 2 nodes x 8KB
#define SMEM_TOTAL 50176

static __device__ __forceinline__ uint32_t smem_u32(const void* p) {
    uint32_t a;
    asm("{ .reg .u64 t; cvta.to.shared.u64 t, %1; cvt.u32.u64 %0, t; }" : "=r"(a) : "l"(p));
    return a;
}

static __device__ __forceinline__ void ldsm4(uint32_t* r, uint32_t addr) {
    asm volatile("ldmatrix.sync.aligned.m8n8.x4.shared.b16 {%0,%1,%2,%3}, [%4];"
                 : "=r"(r[0]), "=r"(r[1]), "=r"(r[2]), "=r"(r[3]) : "r"(addr));
}

static __device__ __forceinline__ void mma16816(float* c, const uint32_t* a,
                                                const uint32_t* b) {
    asm volatile(
        "mma.sync.aligned.m16n8k16.row.col.f32.f16.f16.f32 "
        "{%0,%1,%2,%3}, {%4,%5,%6,%7}, {%8,%9}, {%0,%1,%2,%3};"
        : "+f"(c[0]), "+f"(c[1]), "+f"(c[2]), "+f"(c[3])
        : "r"(a[0]), "r"(a[1]), "r"(a[2]), "r"(a[3]), "r"(b[0]), "r"(b[1]));
}

// float4 -> fp16 hi (uint2) and fp16 lo residual (uint2)
static __device__ __forceinline__ void split4h(float4 v, uint2& hi, uint2& lo) {
    __half h0 = __float2half_rn(v.x), h1 = __float2half_rn(v.y);
    __half h2 = __float2half_rn(v.z), h3 = __float2half_rn(v.w);
    __half2 hp0 = __halves2half2(h0, h1);
    __half2 hp1 = __halves2half2(h2, h3);
    __half2 lp0 = __floats2half2_rn(v.x - __half2float(h0), v.y - __half2float(h1));
    __half2 lp1 = __floats2half2_rn(v.z - __half2float(h2), v.w - __half2float(h3));
    hi.x = *(uint32_t*)&hp0; hi.y = *(uint32_t*)&hp1;
    lo.x = *(uint32_t*)&lp0; lo.y = *(uint32_t*)&lp1;
}

// ---- prep: X -> fp16 hi/lo; W1*adj -> fp16 ----
__global__ __launch_bounds__(NT)
void prep_kernel(const float* __restrict__ X,
                 const float* __restrict__ Adj,
                 const float* __restrict__ W1)
{
    int gid = blockIdx.x * NT + threadIdx.x;
    if (gid < 262144) {                       // X: 16384*64/4 float4s
        float4 v = ((const float4*)X)[gid];
        uint2 hi, lo;
        split4h(v, hi, lo);
        ((uint2*)Xhi_g)[gid] = hi;
        ((uint2*)Xlo_g)[gid] = lo;
    } else {                                  // W: 64*64*64/4 float4s
        int j = gid - 262144;                 // 0..65535
        int i  = j >> 10;
        int d4 = j & 15;
        float4 v = ((const float4*)W1)[j];
        float4 a = ((const float4*)Adj)[i * 16 + d4];
        v.x *= a.x; v.y *= a.y; v.z *= a.z; v.w *= a.w;
        __half2 p0 = __floats2half2_rn(v.x, v.y);
        __half2 p1 = __floats2half2_rn(v.z, v.w);
        uint2 w; w.x = *(uint32_t*)&p0; w.y = *(uint32_t*)&p1;
        ((uint2*)Wf_g)[j] = w;
    }
}

// ---- main GEMM ----
__global__ __launch_bounds__(NT, 2)
void tp_kernel(const float* __restrict__ W2, float* __restrict__ out)
{
    extern __shared__ char smem[];
    const uint32_t sb = smem_u32(smem);
    const int tid = threadIdx.x;
    const int wid = tid >> 5;
    const int l   = tid & 31;
    const int i0   = blockIdx.x * NPB;     // node pair (fastest -> X L2 reuse)
    const int row0 = blockIdx.y * TB;

    // ---- stage W2 ----
    if (tid < 128) ((float*)(smem + OFF_W2))[tid] = W2[i0 * 64 + tid];

    // ---- stage X hi/lo tile (rows are 128B; swizzled 16B chunks) ----
    {
        const uint4* srcHi = (const uint4*)Xhi_g + row0 * 8;
        const uint4* srcLo = (const uint4*)Xlo_g + row0 * 8;
        #pragma unroll
        for (int it = 0; it < 4; ++it) {
            int c   = tid + it * NT;       // 0..1023
            int row = c >> 3, k16 = c & 7;
            uint32_t dst = OFF_XHI + row * 128 + ((k16 ^ (row & 7)) << 4);
            *(uint4*)(smem + dst)         = srcHi[c];
            *(uint4*)(smem + dst + 16384) = srcLo[c];
        }
    }
    // ---- stage W for 2 nodes (single fp16 buffer) ----
    {
        #pragma unroll
        for (int it = 0; it < 4; ++it) {
            int c  = tid + it * NT;        // 0..1023
            int n  = c >> 9, r = (c >> 3) & 63, k16 = c & 7;
            const uint4* src = (const uint4*)Wf_g + ((i0 + n) * 64 + r) * 8 + k16;
            uint32_t dst = OFF_W + n * 8192 + r * 128 + ((k16 ^ (r & 7)) << 4);
            *(uint4*)(smem + dst) = *src;
        }
    }
    __syncthreads();

    // ---- per-warp tile: node = wid>>2, rows rowbase..+31 ----
    const int node    = wid >> 2;
    const int rowbase = (wid & 3) * 32;

    // A (16x16 m-tiles): lane -> row rowbase+mt*16+(l&15), k-half = l>>4
    uint32_t aoff[2], asw[2];
    #pragma unroll
    for (int mt = 0; mt < 2; ++mt) {
        int arow = rowbase + mt * 16 + (l & 15);
        aoff[mt] = sb + OFF_XHI + arow * 128;
        asw[mt]  = arow & 7;
    }
    const uint32_t ahalf = (l >> 4) & 1;
    // B (16n x 16k groups): lane -> n-row, k-half = (l>>3)&1
    uint32_t boff[4], bsw[4];
    #pragma unroll
    for (int g = 0; g < 4; ++g) {
        int brow = g * 16 + ((l >> 4) & 1) * 8 + (l & 7);
        boff[g] = sb + OFF_W + node * 8192 + brow * 128;
        bsw[g]  = brow & 7;
    }
    const uint32_t bhalf = (l >> 3) & 1;

    float acc[2][8][4];
    #pragma unroll
    for (int mt = 0; mt < 2; ++mt)
        #pragma unroll
        for (int n = 0; n < 8; ++n)
            #pragma unroll
            for (int q = 0; q < 4; ++q) acc[mt][n][q] = 0.f;

    #pragma unroll
    for (int ks = 0; ks < 4; ++ks) {
        uint32_t xhi[2][4], xlo[2][4];
        #pragma unroll
        for (int mt = 0; mt < 2; ++mt) {
            uint32_t addr = aoff[mt] + (((ks * 2 + ahalf) ^ asw[mt]) << 4);
            ldsm4(xhi[mt], addr);
            ldsm4(xlo[mt], addr + 16384);
        }
        uint32_t wv[4][4];
        #pragma unroll
        for (int g = 0; g < 4; ++g) {
            uint32_t addr = boff[g] + (((ks * 2 + bhalf) ^ bsw[g]) << 4);
            ldsm4(wv[g], addr);
        }
        #pragma unroll
        for (int mt = 0; mt < 2; ++mt)
            #pragma unroll
            for (int n = 0; n < 8; ++n) {
                const uint32_t* bp = &wv[n >> 1][(n & 1) * 2];
                mma16816(acc[mt][n], xhi[mt], bp);
                mma16816(acc[mt][n], xlo[mt], bp);
            }
    }

    // ---- epilogue: relu + dot W2, reduce across lane quads, store ----
    const float* W2s = (const float*)(smem + OFF_W2) + node * 64;
    #pragma unroll
    for (int mt = 0; mt < 2; ++mt) {
        float s0 = 0.f, s1 = 0.f;
        #pragma unroll
        for (int n = 0; n < 8; ++n) {
            float2 w = *(const float2*)(W2s + n * 8 + (l & 3) * 2);
            s0 = fmaf(fmaxf(acc[mt][n][0], 0.f), w.x, s0);
            s0 = fmaf(fmaxf(acc[mt][n][1], 0.f), w.y, s0);
            s1 = fmaf(fmaxf(acc[mt][n][2], 0.f), w.x, s1);
            s1 = fmaf(fmaxf(acc[mt][n][3], 0.f), w.y, s1);
        }
        s0 += __shfl_xor_sync(0xffffffffu, s0, 1);
        s0 += __shfl_xor_sync(0xffffffffu, s0, 2);
        s1 += __shfl_xor_sync(0xffffffffu, s1, 1);
        s1 += __shfl_xor_sync(0xffffffffu, s1, 2);
        if ((l & 3) == 0) {
            int grow = row0 + rowbase + mt * 16 + (l >> 2);
            out[(size_t)grow * 64 + i0 + node]       = s0;
            out[(size_t)(grow + 8) * 64 + i0 + node] = s1;
        }
    }
}

extern "C" void kernel_launch(void* const* d_in, const int* in_sizes, int n_in,
                              void* d_out, int out_size) {
    const float* X   = (const float*)d_in[0];  // [16384, 64]
    const float* Adj = (const float*)d_in[1];  // [64, 64]
    const float* W1  = (const float*)d_in[2];  // [64, 64, 64] (i,h,d)
    const float* W2  = (const float*)d_in[3];  // [64, 64]
    float* out = (float*)d_out;                // [16384, 64]

    prep_kernel<<<1280, NT>>>(X, Adj, W1);

    cudaFuncSetAttribute(tp_kernel, cudaFuncAttributeMaxDynamicSharedMemorySize,
                         SMEM_TOTAL);
    dim3 grid(64 / NPB, 16384 / TB);
    tp_kernel<<<grid, NT, SMEM_TOTAL>>>(W2, out);
}

// round 6
// speedup vs baseline: 5.8689x; 1.3231x over previous
#include <cuda_runtime.h>
#include <cuda_fp16.h>
#include <cstdint>

// out[b,i] = sum_h W2[i,h] * relu( sum_d X[b,d]*Adj[i,d]*W1[i,h,d] )
// B=16384, D=64, H=64.
//
// Single-term fp16 HMMA (mma.sync m16n8k16 f32.f16.f16):
//   acc_f32 += fp16(X) * fp16(W1*adj)    (rel_err ~3e-4, gate is 1e-3)
// Prep kernel converts X and W'=W1*adj to fp16 once. Main kernel: block =
// (2 nodes, 128 rows), 8 warps; warp = 32 rows x 64 h. Staging via cp.async.

#define NT  256
#define NPB 2
#define TB  128

// ---- device-global fp16 buffers (prep output) ----
static __device__ __align__(16) __half Xf_g[16384 * 64];
static __device__ __align__(16) __half Wf_g[64 * 64 * 64];

// ---- main-kernel smem layout (bytes) ----
#define OFF_W2   0        // 128 floats
#define OFF_X    1024     // 128 rows x 128B, swizzled
#define OFF_W    17408    // 2 nodes x 8KB, swizzled
#define SMEM_TOTAL 33792

static __device__ __forceinline__ uint32_t smem_u32(const void* p) {
    uint32_t a;
    asm("{ .reg .u64 t; cvta.to.shared.u64 t, %1; cvt.u32.u64 %0, t; }" : "=r"(a) : "l"(p));
    return a;
}

static __device__ __forceinline__ void cp16(uint32_t dst, const void* src) {
    asm volatile("cp.async.ca.shared.global [%0], [%1], 16;"
                 :: "r"(dst), "l"(src) : "memory");
}

static __device__ __forceinline__ void ldsm4(uint32_t* r, uint32_t addr) {
    asm volatile("ldmatrix.sync.aligned.m8n8.x4.shared.b16 {%0,%1,%2,%3}, [%4];"
                 : "=r"(r[0]), "=r"(r[1]), "=r"(r[2]), "=r"(r[3]) : "r"(addr));
}

static __device__ __forceinline__ void mma16816(float* c, const uint32_t* a,
                                                const uint32_t* b) {
    asm volatile(
        "mma.sync.aligned.m16n8k16.row.col.f32.f16.f16.f32 "
        "{%0,%1,%2,%3}, {%4,%5,%6,%7}, {%8,%9}, {%0,%1,%2,%3};"
        : "+f"(c[0]), "+f"(c[1]), "+f"(c[2]), "+f"(c[3])
        : "r"(a[0]), "r"(a[1]), "r"(a[2]), "r"(a[3]), "r"(b[0]), "r"(b[1]));
}

// ---- prep: X -> fp16; W1*adj -> fp16 ----
__global__ __launch_bounds__(NT)
void prep_kernel(const float* __restrict__ X,
                 const float* __restrict__ Adj,
                 const float* __restrict__ W1)
{
    int gid = blockIdx.x * NT + threadIdx.x;
    if (gid < 262144) {                       // X: 16384*64/4 float4s
        float4 v = ((const float4*)X)[gid];
        __half2 p0 = __floats2half2_rn(v.x, v.y);
        __half2 p1 = __floats2half2_rn(v.z, v.w);
        uint2 r; r.x = *(uint32_t*)&p0; r.y = *(uint32_t*)&p1;
        ((uint2*)Xf_g)[gid] = r;
    } else {                                  // W: 64*64*64/4 float4s
        int j = gid - 262144;                 // 0..65535
        int i  = j >> 10;
        int d4 = j & 15;
        float4 v = ((const float4*)W1)[j];
        float4 a = ((const float4*)Adj)[i * 16 + d4];
        v.x *= a.x; v.y *= a.y; v.z *= a.z; v.w *= a.w;
        __half2 p0 = __floats2half2_rn(v.x, v.y);
        __half2 p1 = __floats2half2_rn(v.z, v.w);
        uint2 r; r.x = *(uint32_t*)&p0; r.y = *(uint32_t*)&p1;
        ((uint2*)Wf_g)[j] = r;
    }
}

// ---- main GEMM ----
__global__ __launch_bounds__(NT, 2)
void tp_kernel(const float* __restrict__ W2, float* __restrict__ out)
{
    extern __shared__ char smem[];
    const uint32_t sb = smem_u32(smem);
    const int tid = threadIdx.x;
    const int wid = tid >> 5;
    const int l   = tid & 31;
    const int i0   = blockIdx.x * NPB;     // node pair (fastest -> X L2 reuse)
    const int row0 = blockIdx.y * TB;

    // ---- stage X tile via cp.async (16B swizzled chunks) ----
    {
        const char* xsrc = (const char*)(Xf_g + (size_t)row0 * 64);
        #pragma unroll
        for (int it = 0; it < 4; ++it) {
            int c   = tid + it * NT;       // 0..1023
            int row = c >> 3, k16 = c & 7;
            uint32_t dst = sb + OFF_X + row * 128 + ((k16 ^ (row & 7)) << 4);
            cp16(dst, xsrc + c * 16);
        }
    }
    // ---- stage W for 2 nodes via cp.async ----
    {
        const char* wsrc = (const char*)(Wf_g + (size_t)i0 * 4096);
        #pragma unroll
        for (int it = 0; it < 4; ++it) {
            int c = tid + it * NT;         // 0..1023 (n,r,k16 lexicographic)
            int r = (c >> 3) & 63, k16 = c & 7;
            uint32_t dst = sb + OFF_W + (c >> 9) * 8192 + r * 128
                         + ((k16 ^ (r & 7)) << 4);
            cp16(dst, wsrc + c * 16);
        }
    }
    asm volatile("cp.async.commit_group;" ::: "memory");

    // ---- stage W2 (plain) ----
    if (tid < 128) ((float*)(smem + OFF_W2))[tid] = W2[i0 * 64 + tid];

    asm volatile("cp.async.wait_group 0;" ::: "memory");
    __syncthreads();

    // ---- per-warp tile: node = wid>>2, rows rowbase..+31 ----
    const int node    = wid >> 2;
    const int rowbase = (wid & 3) * 32;

    // A (16x16 m-tiles): lane -> row rowbase+mt*16+(l&15), k-half = l>>4
    uint32_t aoff[2], asw[2];
    #pragma unroll
    for (int mt = 0; mt < 2; ++mt) {
        int arow = rowbase + mt * 16 + (l & 15);
        aoff[mt] = sb + OFF_X + arow * 128;
        asw[mt]  = arow & 7;
    }
    const uint32_t ahalf = (l >> 4) & 1;
    // B (16n x 16k groups): lane -> n-row, k-half = (l>>3)&1
    uint32_t boff[4], bsw[4];
    #pragma unroll
    for (int g = 0; g < 4; ++g) {
        int brow = g * 16 + ((l >> 4) & 1) * 8 + (l & 7);
        boff[g] = sb + OFF_W + node * 8192 + brow * 128;
        bsw[g]  = brow & 7;
    }
    const uint32_t bhalf = (l >> 3) & 1;

    float acc[2][8][4];
    #pragma unroll
    for (int mt = 0; mt < 2; ++mt)
        #pragma unroll
        for (int n = 0; n < 8; ++n)
            #pragma unroll
            for (int q = 0; q < 4; ++q) acc[mt][n][q] = 0.f;

    #pragma unroll
    for (int ks = 0; ks < 4; ++ks) {
        uint32_t xv[2][4];
        #pragma unroll
        for (int mt = 0; mt < 2; ++mt)
            ldsm4(xv[mt], aoff[mt] + (((ks * 2 + ahalf) ^ asw[mt]) << 4));
        uint32_t wv[4][4];
        #pragma unroll
        for (int g = 0; g < 4; ++g)
            ldsm4(wv[g], boff[g] + (((ks * 2 + bhalf) ^ bsw[g]) << 4));
        #pragma unroll
        for (int mt = 0; mt < 2; ++mt)
            #pragma unroll
            for (int n = 0; n < 8; ++n)
                mma16816(acc[mt][n], xv[mt], &wv[n >> 1][(n & 1) * 2]);
    }

    // ---- epilogue: relu + dot W2, reduce across lane quads, store ----
    const float* W2s = (const float*)(smem + OFF_W2) + node * 64;
    #pragma unroll
    for (int mt = 0; mt < 2; ++mt) {
        float s0 = 0.f, s1 = 0.f;
        #pragma unroll
        for (int n = 0; n < 8; ++n) {
            float2 w = *(const float2*)(W2s + n * 8 + (l & 3) * 2);
            s0 = fmaf(fmaxf(acc[mt][n][0], 0.f), w.x, s0);
            s0 = fmaf(fmaxf(acc[mt][n][1], 0.f), w.y, s0);
            s1 = fmaf(fmaxf(acc[mt][n][2], 0.f), w.x, s1);
            s1 = fmaf(fmaxf(acc[mt][n][3], 0.f), w.y, s1);
        }
        s0 += __shfl_xor_sync(0xffffffffu, s0, 1);
        s0 += __shfl_xor_sync(0xffffffffu, s0, 2);
        s1 += __shfl_xor_sync(0xffffffffu, s1, 1);
        s1 += __shfl_xor_sync(0xffffffffu, s1, 2);
        if ((l & 3) == 0) {
            int grow = row0 + rowbase + mt * 16 + (l >> 2);
            out[(size_t)grow * 64 + i0 + node]       = s0;
            out[(size_t)(grow + 8) * 64 + i0 + node] = s1;
        }
    }
}

extern "C" void kernel_launch(void* const* d_in, const int* in_sizes, int n_in,
                              void* d_out, int out_size) {
    const float* X   = (const float*)d_in[0];  // [16384, 64]
    const float* Adj = (const float*)d_in[1];  // [64, 64]
    const float* W1  = (const float*)d_in[2];  // [64, 64, 64] (i,h,d)
    const float* W2  = (const float*)d_in[3];  // [64, 64]
    float* out = (float*)d_out;                // [16384, 64]

    prep_kernel<<<1280, NT>>>(X, Adj, W1);

    cudaFuncSetAttribute(tp_kernel, cudaFuncAttributeMaxDynamicSharedMemorySize,
                         SMEM_TOTAL);
    dim3 grid(64 / NPB, 16384 / TB);
    tp_kernel<<<grid, NT, SMEM_TOTAL>>>(W2, out);
}

// round 7
// speedup vs baseline: 6.1592x; 1.0495x over previous
#include <cuda_runtime.h>
#include <cuda_fp16.h>
#include <cstdint>

// out[b,i] = sum_h W2[i,h] * relu( sum_d X[b,d]*Adj[i,d]*W1[i,h,d] )
// B=16384, D=64, H=64.
//
// Single-term fp16 HMMA (mma.sync m16n8k16 f32.f16.f16), rel_err ~3e-4.
// Block = (2 nodes x 512 rows) = 4 tiles of 128 rows. W resident in smem,
// X tiles double-buffered via cp.async (fill t+1 overlaps compute of t).

#define NT   256
#define NPB  2
#define TB   128
#define TPB  4      // tiles per block

// ---- device-global fp16 buffers (prep output) ----
static __device__ __align__(16) __half Xf_g[16384 * 64];
static __device__ __align__(16) __half Wf_g[64 * 64 * 64];

// ---- main-kernel smem layout (bytes) ----
#define OFF_W2   0        // 128 floats
#define OFF_W    1024     // 2 nodes x 8KB, swizzled
#define OFF_X    17408    // 2 buffers x (128 rows x 128B), swizzled
#define SMEM_TOTAL 50176

static __device__ __forceinline__ uint32_t smem_u32(const void* p) {
    uint32_t a;
    asm("{ .reg .u64 t; cvta.to.shared.u64 t, %1; cvt.u32.u64 %0, t; }" : "=r"(a) : "l"(p));
    return a;
}

static __device__ __forceinline__ void cp16(uint32_t dst, const void* src) {
    asm volatile("cp.async.ca.shared.global [%0], [%1], 16;"
                 :: "r"(dst), "l"(src) : "memory");
}

static __device__ __forceinline__ void ldsm4(uint32_t* r, uint32_t addr) {
    asm volatile("ldmatrix.sync.aligned.m8n8.x4.shared.b16 {%0,%1,%2,%3}, [%4];"
                 : "=r"(r[0]), "=r"(r[1]), "=r"(r[2]), "=r"(r[3]) : "r"(addr));
}

static __device__ __forceinline__ void mma16816(float* c, const uint32_t* a,
                                                const uint32_t* b) {
    asm volatile(
        "mma.sync.aligned.m16n8k16.row.col.f32.f16.f16.f32 "
        "{%0,%1,%2,%3}, {%4,%5,%6,%7}, {%8,%9}, {%0,%1,%2,%3};"
        : "+f"(c[0]), "+f"(c[1]), "+f"(c[2]), "+f"(c[3])
        : "r"(a[0]), "r"(a[1]), "r"(a[2]), "r"(a[3]), "r"(b[0]), "r"(b[1]));
}

// ---- prep: X -> fp16; W1*adj -> fp16 ----
__global__ __launch_bounds__(NT)
void prep_kernel(const float* __restrict__ X,
                 const float* __restrict__ Adj,
                 const float* __restrict__ W1)
{
    int gid = blockIdx.x * NT + threadIdx.x;
    if (gid < 262144) {                       // X: 16384*64/4 float4s
        float4 v = ((const float4*)X)[gid];
        __half2 p0 = __floats2half2_rn(v.x, v.y);
        __half2 p1 = __floats2half2_rn(v.z, v.w);
        uint2 r; r.x = *(uint32_t*)&p0; r.y = *(uint32_t*)&p1;
        ((uint2*)Xf_g)[gid] = r;
    } else {                                  // W: 64*64*64/4 float4s
        int j = gid - 262144;                 // 0..65535
        int i  = j >> 10;
        int d4 = j & 15;
        float4 v = ((const float4*)W1)[j];
        float4 a = ((const float4*)Adj)[i * 16 + d4];
        v.x *= a.x; v.y *= a.y; v.z *= a.z; v.w *= a.w;
        __half2 p0 = __floats2half2_rn(v.x, v.y);
        __half2 p1 = __floats2half2_rn(v.z, v.w);
        uint2 r; r.x = *(uint32_t*)&p0; r.y = *(uint32_t*)&p1;
        ((uint2*)Wf_g)[j] = r;
    }
}

// stage one 128-row X tile into smem buffer (4 cp16 per thread)
static __device__ __forceinline__ void stage_x(uint32_t sb, int buf,
                                               const char* xsrc, int tid) {
    uint32_t base = sb + OFF_X + buf * 16384;
    #pragma unroll
    for (int it = 0; it < 4; ++it) {
        int c   = tid + it * NT;           // 0..1023
        int row = c >> 3, k16 = c & 7;
        cp16(base + row * 128 + ((k16 ^ (row & 7)) << 4), xsrc + c * 16);
    }
}

// ---- main GEMM ----
__global__ __launch_bounds__(NT, 2)
void tp_kernel(const float* __restrict__ W2, float* __restrict__ out)
{
    extern __shared__ char smem[];
    const uint32_t sb = smem_u32(smem);
    const int tid = threadIdx.x;
    const int wid = tid >> 5;
    const int l   = tid & 31;
    const int i0   = blockIdx.x * NPB;          // node pair (fastest -> L2 reuse)
    const int row0 = blockIdx.y * (TB * TPB);   // 512-row group

    // ---- stage W for 2 nodes (resident all block) ----
    {
        const char* wsrc = (const char*)(Wf_g + (size_t)i0 * 4096);
        #pragma unroll
        for (int it = 0; it < 4; ++it) {
            int c = tid + it * NT;         // 0..1023
            int r = (c >> 3) & 63, k16 = c & 7;
            uint32_t dst = sb + OFF_W + (c >> 9) * 8192 + r * 128
                         + ((k16 ^ (r & 7)) << 4);
            cp16(dst, wsrc + c * 16);
        }
    }
    // ---- stage X tile 0 ----
    const char* xbase = (const char*)(Xf_g + (size_t)row0 * 64);
    stage_x(sb, 0, xbase, tid);
    asm volatile("cp.async.commit_group;" ::: "memory");

    // ---- stage W2 (plain) ----
    if (tid < 128) ((float*)(smem + OFF_W2))[tid] = W2[i0 * 64 + tid];

    // ---- per-warp constants ----
    const int node    = wid >> 2;
    const int rowbase = (wid & 3) * 32;

    uint32_t aoff[2], asw[2];                  // A: relative to X buffer base
    #pragma unroll
    for (int mt = 0; mt < 2; ++mt) {
        int arow = rowbase + mt * 16 + (l & 15);
        aoff[mt] = sb + OFF_X + arow * 128;
        asw[mt]  = arow & 7;
    }
    const uint32_t ahalf = (l >> 4) & 1;
    uint32_t boff[4], bsw[4];
    #pragma unroll
    for (int g = 0; g < 4; ++g) {
        int brow = g * 16 + ((l >> 4) & 1) * 8 + (l & 7);
        boff[g] = sb + OFF_W + node * 8192 + brow * 128;
        bsw[g]  = brow & 7;
    }
    const uint32_t bhalf = (l >> 3) & 1;
    const float* W2s = (const float*)(smem + OFF_W2) + node * 64;

    #pragma unroll
    for (int t = 0; t < TPB; ++t) {
        asm volatile("cp.async.wait_group 0;" ::: "memory");
        __syncthreads();

        // prefetch next X tile (overlaps this tile's MMAs)
        if (t + 1 < TPB) {
            stage_x(sb, (t + 1) & 1, xbase + (size_t)(t + 1) * TB * 128, tid);
            asm volatile("cp.async.commit_group;" ::: "memory");
        }

        const uint32_t xb = (uint32_t)((t & 1) * 16384);

        float acc[2][8][4];
        #pragma unroll
        for (int mt = 0; mt < 2; ++mt)
            #pragma unroll
            for (int n = 0; n < 8; ++n)
                #pragma unroll
                for (int q = 0; q < 4; ++q) acc[mt][n][q] = 0.f;

        #pragma unroll
        for (int ks = 0; ks < 4; ++ks) {
            uint32_t xv[2][4];
            #pragma unroll
            for (int mt = 0; mt < 2; ++mt)
                ldsm4(xv[mt], aoff[mt] + xb + (((ks * 2 + ahalf) ^ asw[mt]) << 4));
            uint32_t wv[4][4];
            #pragma unroll
            for (int g = 0; g < 4; ++g)
                ldsm4(wv[g], boff[g] + (((ks * 2 + bhalf) ^ bsw[g]) << 4));
            #pragma unroll
            for (int mt = 0; mt < 2; ++mt)
                #pragma unroll
                for (int n = 0; n < 8; ++n)
                    mma16816(acc[mt][n], xv[mt], &wv[n >> 1][(n & 1) * 2]);
        }

        // ---- epilogue: relu + dot W2, quad reduce, store ----
        #pragma unroll
        for (int mt = 0; mt < 2; ++mt) {
            float s0 = 0.f, s1 = 0.f;
            #pragma unroll
            for (int n = 0; n < 8; ++n) {
                float2 w = *(const float2*)(W2s + n * 8 + (l & 3) * 2);
                s0 = fmaf(fmaxf(acc[mt][n][0], 0.f), w.x, s0);
                s0 = fmaf(fmaxf(acc[mt][n][1], 0.f), w.y, s0);
                s1 = fmaf(fmaxf(acc[mt][n][2], 0.f), w.x, s1);
                s1 = fmaf(fmaxf(acc[mt][n][3], 0.f), w.y, s1);
            }
            s0 += __shfl_xor_sync(0xffffffffu, s0, 1);
            s0 += __shfl_xor_sync(0xffffffffu, s0, 2);
            s1 += __shfl_xor_sync(0xffffffffu, s1, 1);
            s1 += __shfl_xor_sync(0xffffffffu, s1, 2);
            if ((l & 3) == 0) {
                int grow = row0 + t * TB + rowbase + mt * 16 + (l >> 2);
                out[(size_t)grow * 64 + i0 + node]       = s0;
                out[(size_t)(grow + 8) * 64 + i0 + node] = s1;
            }
        }
    }
}

extern "C" void kernel_launch(void* const* d_in, const int* in_sizes, int n_in,
                              void* d_out, int out_size) {
    const float* X   = (const float*)d_in[0];  // [16384, 64]
    const float* Adj = (const float*)d_in[1];  // [64, 64]
    const float* W1  = (const float*)d_in[2];  // [64, 64, 64] (i,h,d)
    const float* W2  = (const float*)d_in[3];  // [64, 64]
    float* out = (float*)d_out;                // [16384, 64]

    prep_kernel<<<1280, NT>>>(X, Adj, W1);

    cudaFuncSetAttribute(tp_kernel, cudaFuncAttributeMaxDynamicSharedMemorySize,
                         SMEM_TOTAL);
    dim3 grid(64 / NPB, 16384 / (TB * TPB));
    tp_kernel<<<grid, NT, SMEM_TOTAL>>>(W2, out);
}